// round 6
// baseline (speedup 1.0000x reference)
#include <cuda_runtime.h>
#include <cuda_bf16.h>
#include <cstdint>

#define NB 16
#define NC 256
#define NT 2048
#define NROWS (NB*NT)          // 32768
#define NCODES 8192
#define NQ (NB*NC*NT)          // 8388608
#define CANDMAX 64
#define MARGIN 1.0e-3f
#define CHUNKS_PER_LAUNCH 16

// ---------------- device scratch ----------------
__device__ float g_zt[(size_t)NROWS * NC];
__device__ __nv_bfloat16 g_ztb[(size_t)NROWS * NC];
__device__ __nv_bfloat16 g_cbb[(size_t)NCODES * NC];
__device__ float g_zz[NROWS];
__device__ float g_ee[NCODES];
__device__ int   g_idx[NROWS];
__device__ float g_losspart[NQ / 256];
__device__ float g_cand_s[(size_t)NROWS * CANDMAX];
__device__ int   g_cand_c[(size_t)NROWS * CANDMAX];
__device__ unsigned int g_bestu[NROWS];
__device__ int   g_cnt[NROWS];

// ---------------- helpers ----------------
__device__ __forceinline__ uint32_t smem_u32(const void* p) {
    uint32_t a;
    asm("{ .reg .u64 t; cvta.to.shared.u64 t, %1; cvt.u32.u64 %0, t; }" : "=r"(a) : "l"(p));
    return a;
}
__device__ __forceinline__ void cp16(uint32_t dst, const void* src) {
    unsigned long long g = __cvta_generic_to_global(src);
    asm volatile("cp.async.cg.shared.global [%0], [%1], 16;" :: "r"(dst), "l"(g) : "memory");
}
#define CP_COMMIT() asm volatile("cp.async.commit_group;" ::: "memory")
#define CP_WAIT0()  asm volatile("cp.async.wait_group 0;" ::: "memory")
#define SWZ(x) ((x) ^ (((x) >> 3) & 0x70))

__device__ __forceinline__ void ldsm_x4(uint32_t* r, uint32_t a) {
    asm volatile("ldmatrix.sync.aligned.m8n8.x4.shared.b16 {%0,%1,%2,%3}, [%4];"
        : "=r"(r[0]), "=r"(r[1]), "=r"(r[2]), "=r"(r[3]) : "r"(a));
}
__device__ __forceinline__ void mma16816(float* c, const uint32_t* a, uint32_t b0, uint32_t b1) {
    asm volatile("mma.sync.aligned.m16n8k16.row.col.f32.bf16.bf16.f32 "
        "{%0,%1,%2,%3}, {%4,%5,%6,%7}, {%8,%9}, {%0,%1,%2,%3};"
        : "+f"(c[0]), "+f"(c[1]), "+f"(c[2]), "+f"(c[3])
        : "r"(a[0]), "r"(a[1]), "r"(a[2]), "r"(a[3]), "r"(b0), "r"(b1));
}

#define A_OFF   1024
#define B_OFF   66560
#define EE_OFF  197632
#define SMEMT   230400
#define NTHREADS 512

__device__ __forceinline__ uint32_t tile_addr(uint32_t base, int r, int c) {
    return base + ((c >> 6) << 14) + ((r >> 3) << 10) + SWZ((r & 7) * 128 + (c & 63) * 2);
}

// ---------------- prep kernels ----------------
__global__ void k_transpose(const float* __restrict__ z) {
    __shared__ float tile[64][65];
    int r0 = blockIdx.x * 64;
    int b = r0 >> 11, t0 = r0 & 2047;
    const float* zb = z + (size_t)b * NC * NT;
    for (int c0 = 0; c0 < NC; c0 += 64) {
        for (int i = threadIdx.x; i < 64 * 64; i += 256) {
            int cl = i >> 6, tl = i & 63;
            tile[cl][tl] = zb[(size_t)(c0 + cl) * NT + t0 + tl];
        }
        __syncthreads();
        for (int i = threadIdx.x; i < 64 * 64; i += 256) {
            int rl = i >> 6, cl = i & 63;
            float v = tile[cl][rl];
            size_t o = (size_t)(r0 + rl) * NC + c0 + cl;
            g_zt[o] = v;
            g_ztb[o] = __float2bfloat16(v);
        }
        __syncthreads();
    }
}

__global__ void k_prep(const float* __restrict__ cb) {
    int i = blockIdx.x * 256 + threadIdx.x;
    g_cbb[i] = __float2bfloat16(cb[i]);
    if (i < NROWS) { g_cnt[i] = 0; g_bestu[i] = 0x7F800000u; }
}

__global__ void k_norms(const float* __restrict__ cb) {
    int gr = blockIdx.x * 8 + (threadIdx.x >> 5);
    int lane = threadIdx.x & 31;
    const float* src;
    if (gr < NROWS) src = g_zt + (size_t)gr * NC;
    else            src = cb + (size_t)(gr - NROWS) * NC;
    const float4* p = reinterpret_cast<const float4*>(src);
    float s = 0.f;
#pragma unroll
    for (int j = 0; j < 2; j++) {
        float4 v = p[lane + 32 * j];
        s += v.x * v.x + v.y * v.y + v.z * v.z + v.w * v.w;
    }
#pragma unroll
    for (int o = 16; o > 0; o >>= 1) s += __shfl_xor_sync(0xffffffffu, s, o);
    if (lane == 0) { if (gr < NROWS) g_zz[gr] = s; else g_ee[gr - NROWS] = s; }
}

// load one 128x256-bf16 tile (64KB) into swizzled smem via cp.async
__device__ __forceinline__ void issue_tile(const __nv_bfloat16* src, uint32_t base, int tid) {
    const char* s0 = (const char*)src;
    for (int idx = tid; idx < 4096; idx += NTHREADS) {
        int r = idx >> 5, ch = idx & 31;
        cp16(tile_addr(base, r, ch * 8), s0 + (size_t)r * 512 + ch * 16);
    }
}

// ---------------- screening: 512 threads, 16 warps (4Mx4N grid of 32x32) ----------------
__global__ void __launch_bounds__(NTHREADS, 1) k_screen(int c0) {
    extern __shared__ char smem[];
    uint32_t sb = smem_u32(smem);
    const int tid = threadIdx.x, lane = tid & 31, wid = tid >> 5;
    const int wm = wid >> 2, wn = wid & 3;     // 4 (M) x 4 (N)
    const int r0 = blockIdx.x * 128;
    const int g4 = lane >> 2, q4 = lane & 3;

    float* ees = (float*)(smem + EE_OFF);
    for (int i = tid; i < NCODES; i += NTHREADS) ees[i] = g_ee[i];

    issue_tile(g_ztb + (size_t)r0 * NC, sb + A_OFF, tid);
    issue_tile(g_cbb + (size_t)c0 * 128 * NC, sb + B_OFF + (c0 & 1) * 65536, tid);
    CP_COMMIT();

    float zzr[2][2], lb[2][2];
#pragma unroll
    for (int mt = 0; mt < 2; mt++)
#pragma unroll
        for (int h = 0; h < 2; h++) {
            int row = r0 + wm * 32 + mt * 16 + h * 8 + g4;
            zzr[mt][h] = g_zz[row];
            lb[mt][h] = __uint_as_float(g_bestu[row]);
        }

    const int lrow = ((lane >> 3) & 1) * 8 + (lane & 7);
    const int lcol = (lane >> 4) * 8;

    for (int c = c0; c < c0 + CHUNKS_PER_LAUNCH; c++) {
        CP_WAIT0();
        __syncthreads();
        if (c + 1 < c0 + CHUNKS_PER_LAUNCH)
            issue_tile(g_cbb + (size_t)(c + 1) * 128 * NC, sb + B_OFF + ((c + 1) & 1) * 65536, tid);
        CP_COMMIT();

        const uint32_t bbase = sb + B_OFF + (c & 1) * 65536;
        const uint32_t abase = sb + A_OFF;
        float acc[2][4][4];
#pragma unroll
        for (int mt = 0; mt < 2; mt++)
#pragma unroll
            for (int nt = 0; nt < 4; nt++)
#pragma unroll
                for (int e = 0; e < 4; e++) acc[mt][nt][e] = 0.f;

#pragma unroll
        for (int kk = 0; kk < 16; kk++) {
            int k0 = kk * 16 + lcol;
            uint32_t a[2][4], b[2][4];
#pragma unroll
            for (int mt = 0; mt < 2; mt++)
                ldsm_x4(a[mt], tile_addr(abase, wm * 32 + mt * 16 + lrow, k0));
#pragma unroll
            for (int p = 0; p < 2; p++)
                ldsm_x4(b[p], tile_addr(bbase, wn * 32 + p * 16 + lrow, k0));
#pragma unroll
            for (int mt = 0; mt < 2; mt++)
#pragma unroll
                for (int nt = 0; nt < 4; nt++) {
                    int p = nt >> 1, o = nt & 1;
                    mma16816(acc[mt][nt], a[mt], b[p][o], b[p][o + 2]);
                }
        }

        // epilogue: scores, per-row running min, candidate append
        float nb[2][2];
#pragma unroll
        for (int mt = 0; mt < 2; mt++)
#pragma unroll
            for (int h = 0; h < 2; h++) {
                float zze = zzr[mt][h];
                float m = 3.0e38f;
#pragma unroll
                for (int nt = 0; nt < 4; nt++)
#pragma unroll
                    for (int e = 0; e < 2; e++) {
                        int code = c * 128 + wn * 32 + nt * 8 + q4 * 2 + e;
                        float s = fmaf(-2.0f, acc[mt][nt][h * 2 + e], zze + ees[code]);
                        acc[mt][nt][h * 2 + e] = s;
                        m = fminf(m, s);
                    }
                m = fminf(m, __shfl_xor_sync(0xffffffffu, m, 1));
                m = fminf(m, __shfl_xor_sync(0xffffffffu, m, 2));
                nb[mt][h] = fminf(lb[mt][h], m);
            }
#pragma unroll
        for (int mt = 0; mt < 2; mt++)
#pragma unroll
            for (int h = 0; h < 2; h++) {
                float thr = nb[mt][h] + MARGIN;
                int row = r0 + wm * 32 + mt * 16 + h * 8 + g4;
#pragma unroll
                for (int nt = 0; nt < 4; nt++)
#pragma unroll
                    for (int e = 0; e < 2; e++) {
                        float s = acc[mt][nt][h * 2 + e];
                        if (s < thr) {
                            int code = c * 128 + wn * 32 + nt * 8 + q4 * 2 + e;
                            int slot = atomicAdd(&g_cnt[row], 1);
                            if (slot < CANDMAX) {
                                g_cand_s[(size_t)row * CANDMAX + slot] = s;
                                g_cand_c[(size_t)row * CANDMAX + slot] = code;
                            }
                            atomicMin(&g_bestu[row], __float_as_uint(s));
                        }
                    }
                lb[mt][h] = nb[mt][h];
            }
    }
}

// ---------------- exact fp32 rescore ----------------
__global__ void k_rescore(const float* __restrict__ cb) {
    int row = blockIdx.x * 8 + (threadIdx.x >> 5);
    int lane = threadIdx.x & 31;
    const float4* zr = reinterpret_cast<const float4*>(g_zt + (size_t)row * NC);
    float4 z0 = zr[lane * 2], z1 = zr[lane * 2 + 1];
    float zzr = g_zz[row];
    int cnt = g_cnt[row];
    float bs = __uint_as_float(g_bestu[row]);
    unsigned long long bkey = ~0ull;

    auto eval = [&](int code) {
        const float4* er = reinterpret_cast<const float4*>(cb + (size_t)code * NC);
        float4 e0 = er[lane * 2], e1 = er[lane * 2 + 1];
        float p = z0.x * e0.x + z0.y * e0.y + z0.z * e0.z + z0.w * e0.w
                + z1.x * e1.x + z1.y * e1.y + z1.z * e1.z + z1.w * e1.w;
#pragma unroll
        for (int o = 16; o > 0; o >>= 1) p += __shfl_xor_sync(0xffffffffu, p, o);
        float d = __fadd_rn(__fadd_rn(zzr, g_ee[code]), -2.0f * p);
        unsigned long long key =
            ((unsigned long long)__float_as_uint(d) << 13) | (unsigned long long)code;
        if (key < bkey) bkey = key;
    };

    if (cnt > CANDMAX) {
        for (int code = 0; code < NCODES; code++) eval(code);
    } else {
        size_t crow = (size_t)row * CANDMAX;
        for (int i = 0; i < cnt; i++) {
            float si = g_cand_s[crow + i];
            if (si > bs + MARGIN) continue;
            eval(g_cand_c[crow + i]);
        }
    }
    if (lane == 0) g_idx[row] = (int)(bkey & 8191u);
}

__global__ void k_output(const float* __restrict__ z, const float* __restrict__ cb,
                         float* __restrict__ out) {
    __shared__ float warp_s[8];
    int e = blockIdx.x * 256 + threadIdx.x;
    int t = e & 2047, bc = e >> 11, c = bc & 255, b = bc >> 8;
    int code = g_idx[b * 2048 + t];
    float v = z[e];
    float zq = cb[(size_t)code * NC + c];
    float d = zq - v;
    out[e] = v + d;
    float s = d * d;
#pragma unroll
    for (int o = 16; o > 0; o >>= 1) s += __shfl_xor_sync(0xffffffffu, s, o);
    if ((threadIdx.x & 31) == 0) warp_s[threadIdx.x >> 5] = s;
    __syncthreads();
    if (threadIdx.x == 0) {
        float acc = 0.f;
#pragma unroll
        for (int w = 0; w < 8; w++) acc += warp_s[w];
        g_losspart[blockIdx.x] = acc;
    }
}

__global__ void k_final(float* __restrict__ out) {
    if (blockIdx.x < 128) {
        int i = blockIdx.x * 256 + threadIdx.x;
        out[NQ + i] = (float)g_idx[i];
    } else {
        __shared__ double ds[256];
        double a = 0.0;
        for (int i = threadIdx.x; i < NQ / 256; i += 256) a += (double)g_losspart[i];
        ds[threadIdx.x] = a;
        __syncthreads();
        for (int o = 128; o > 0; o >>= 1) {
            if (threadIdx.x < o) ds[threadIdx.x] += ds[threadIdx.x + o];
            __syncthreads();
        }
        if (threadIdx.x == 0) out[NQ + NROWS] = (float)(ds[0] / (double)NQ);
    }
}

extern "C" void kernel_launch(void* const* d_in, const int* in_sizes, int n_in,
                              void* d_out, int out_size) {
    const float* z  = (const float*)d_in[0];
    const float* cb = (const float*)d_in[1];
    float* out = (float*)d_out;
    cudaFuncSetAttribute(k_screen, cudaFuncAttributeMaxDynamicSharedMemorySize, SMEMT);
    k_transpose<<<NROWS / 64, 256>>>(z);
    k_prep<<<(NCODES * NC) / 256, 256>>>(cb);
    k_norms<<<(NROWS + NCODES) / 8, 256>>>(cb);
    k_screen<<<NROWS / 128, NTHREADS, SMEMT>>>(0);
    k_screen<<<NROWS / 128, NTHREADS, SMEMT>>>(16);
    k_screen<<<NROWS / 128, NTHREADS, SMEMT>>>(32);
    k_screen<<<NROWS / 128, NTHREADS, SMEMT>>>(48);
    k_rescore<<<NROWS / 8, 256>>>(cb);
    k_output<<<NQ / 256, 256>>>(z, cb, out);
    k_final<<<129, 256>>>(out);
}

// round 7
// speedup vs baseline: 1.0180x; 1.0180x over previous
#include <cuda_runtime.h>
#include <cuda_bf16.h>
#include <cstdint>

#define NB 16
#define NC 256
#define NT 2048
#define NROWS (NB*NT)          // 32768
#define NCODES 8192
#define NQ (NB*NC*NT)          // 8388608
#define CANDMAX 64
#define MARGIN 1.0e-3f
#define CHUNKS_PER_LAUNCH 16
#define NTHREADS 512

// ---------------- device scratch ----------------
__device__ float g_zt[(size_t)NROWS * NC];
// pre-swizzled smem tile images: 64KB per 128-row tile / 128-code chunk
__device__ __align__(1024) unsigned char g_ztb_sw[(size_t)(NROWS / 128) * 65536];
__device__ __align__(1024) unsigned char g_cbb_sw[(size_t)(NCODES / 128) * 65536];
__device__ __align__(128) float g_zz[NROWS];
__device__ __align__(128) float g_ee[NCODES];
__device__ int   g_idx[NROWS];
__device__ float g_losspart[NQ / 256];
__device__ float g_cand_s[(size_t)NROWS * CANDMAX];
__device__ int   g_cand_c[(size_t)NROWS * CANDMAX];
__device__ unsigned int g_bestu[NROWS];
__device__ int   g_cnt[NROWS];

// ---------------- helpers ----------------
__device__ __forceinline__ uint32_t smem_u32(const void* p) {
    uint32_t a;
    asm("{ .reg .u64 t; cvta.to.shared.u64 t, %1; cvt.u32.u64 %0, t; }" : "=r"(a) : "l"(p));
    return a;
}
#define SWZ(x) ((x) ^ (((x) >> 3) & 0x70))

// swizzled byte offset within a 64KB tile image, for (row-in-tile rl, dim c)
__device__ __forceinline__ uint32_t tile_off(int rl, int c) {
    return ((c >> 6) << 14) + ((rl >> 3) << 10) + SWZ((rl & 7) * 128 + (c & 63) * 2);
}
__device__ __forceinline__ uint32_t tile_addr(uint32_t base, int r, int c) {
    return base + tile_off(r, c);
}

__device__ __forceinline__ void mbar_init(uint32_t m, uint32_t cnt) {
    asm volatile("mbarrier.init.shared.b64 [%0], %1;" :: "r"(m), "r"(cnt) : "memory");
}
__device__ __forceinline__ void mbar_expect_tx(uint32_t m, uint32_t bytes) {
    asm volatile("mbarrier.arrive.expect_tx.shared.b64 _, [%0], %1;" :: "r"(m), "r"(bytes) : "memory");
}
__device__ __forceinline__ void mbar_wait(uint32_t m, int phase) {
    asm volatile(
        "{\n\t.reg .pred P1;\n\t"
        "WL%=:\n\t"
        "mbarrier.try_wait.parity.shared.b64 P1, [%0], %1;\n\t"
        "@P1 bra.uni WD%=;\n\t"
        "bra.uni WL%=;\n\t"
        "WD%=:\n\t}" :: "r"(m), "r"(phase) : "memory");
}
__device__ __forceinline__ void bulk_cp(uint32_t dst, const void* src, uint32_t bytes, uint32_t mbar) {
    unsigned long long g = __cvta_generic_to_global(src);
    asm volatile(
        "cp.async.bulk.shared::cluster.global.mbarrier::complete_tx::bytes [%0], [%1], %2, [%3];"
        :: "r"(dst), "l"(g), "r"(bytes), "r"(mbar) : "memory");
}

__device__ __forceinline__ void ldsm_x4(uint32_t* r, uint32_t a) {
    asm volatile("ldmatrix.sync.aligned.m8n8.x4.shared.b16 {%0,%1,%2,%3}, [%4];"
        : "=r"(r[0]), "=r"(r[1]), "=r"(r[2]), "=r"(r[3]) : "r"(a));
}
__device__ __forceinline__ void mma16816(float* c, const uint32_t* a, uint32_t b0, uint32_t b1) {
    asm volatile("mma.sync.aligned.m16n8k16.row.col.f32.bf16.bf16.f32 "
        "{%0,%1,%2,%3}, {%4,%5,%6,%7}, {%8,%9}, {%0,%1,%2,%3};"
        : "+f"(c[0]), "+f"(c[1]), "+f"(c[2]), "+f"(c[3])
        : "r"(a[0]), "r"(a[1]), "r"(a[2]), "r"(a[3]), "r"(b0), "r"(b1));
}

// smem layout: mbars @0/8/16, A @1024 (64KB), B0/B1 @66560 (2x64KB), ee @197632 (32KB)
#define MB_A    0
#define MB_B    8      // +buf*8
#define A_OFF   1024
#define B_OFF   66560
#define EE_OFF  197632
#define SMEMT   230400

// ---------------- prep kernels ----------------
__global__ void k_transpose(const float* __restrict__ z) {
    __shared__ float tile[64][65];
    int r0 = blockIdx.x * 64;
    int b = r0 >> 11, t0 = r0 & 2047;
    const float* zb = z + (size_t)b * NC * NT;
    for (int c0 = 0; c0 < NC; c0 += 64) {
        for (int i = threadIdx.x; i < 64 * 64; i += 256) {
            int cl = i >> 6, tl = i & 63;
            tile[cl][tl] = zb[(size_t)(c0 + cl) * NT + t0 + tl];
        }
        __syncthreads();
        for (int i = threadIdx.x; i < 64 * 64; i += 256) {
            int rl = i >> 6, cl = i & 63;
            float v = tile[cl][rl];
            int r = r0 + rl, c = c0 + cl;
            g_zt[(size_t)r * NC + c] = v;
            size_t so = (size_t)(r >> 7) * 65536 + tile_off(r & 127, c);
            *reinterpret_cast<__nv_bfloat16*>(g_ztb_sw + so) = __float2bfloat16(v);
        }
        __syncthreads();
    }
}

// codebook bf16 convert into swizzled image + per-row state init
__global__ void k_prep(const float* __restrict__ cb) {
    int i = blockIdx.x * 256 + threadIdx.x;
    int code = i >> 8, c = i & 255;
    size_t so = (size_t)(code >> 7) * 65536 + tile_off(code & 127, c);
    *reinterpret_cast<__nv_bfloat16*>(g_cbb_sw + so) = __float2bfloat16(cb[i]);
    if (i < NROWS) { g_cnt[i] = 0; g_bestu[i] = 0x7F800000u; }
}

__global__ void k_norms(const float* __restrict__ cb) {
    int gr = blockIdx.x * 8 + (threadIdx.x >> 5);
    int lane = threadIdx.x & 31;
    const float* src;
    if (gr < NROWS) src = g_zt + (size_t)gr * NC;
    else            src = cb + (size_t)(gr - NROWS) * NC;
    const float4* p = reinterpret_cast<const float4*>(src);
    float s = 0.f;
#pragma unroll
    for (int j = 0; j < 2; j++) {
        float4 v = p[lane + 32 * j];
        s += v.x * v.x + v.y * v.y + v.z * v.z + v.w * v.w;
    }
#pragma unroll
    for (int o = 16; o > 0; o >>= 1) s += __shfl_xor_sync(0xffffffffu, s, o);
    if (lane == 0) { if (gr < NROWS) g_zz[gr] = s; else g_ee[gr - NROWS] = s; }
}

// ---------------- screening: 512 threads, bulk-copy loads ----------------
__global__ void __launch_bounds__(NTHREADS, 1) k_screen(int c0) {
    extern __shared__ char smem[];
    uint32_t sb = smem_u32(smem);
    const int tid = threadIdx.x, lane = tid & 31, wid = tid >> 5;
    const int wm = wid >> 2, wn = wid & 3;     // 4 (M) x 4 (N)
    const int r0 = blockIdx.x * 128;
    const int g4 = lane >> 2, q4 = lane & 3;

    if (tid == 0) {
        mbar_init(sb + MB_A, 1);
        mbar_init(sb + MB_B, 1);
        mbar_init(sb + MB_B + 8, 1);
    }
    __syncthreads();
    if (tid == 0) {
        mbar_expect_tx(sb + MB_A, 65536 + 32768);
        bulk_cp(sb + A_OFF, g_ztb_sw + (size_t)blockIdx.x * 65536, 65536, sb + MB_A);
        bulk_cp(sb + EE_OFF, g_ee, 32768, sb + MB_A);
        mbar_expect_tx(sb + MB_B, 65536);
        bulk_cp(sb + B_OFF, g_cbb_sw + (size_t)c0 * 65536, 65536, sb + MB_B);
    }

    float zzr[2][2], lb[2][2];
#pragma unroll
    for (int mt = 0; mt < 2; mt++)
#pragma unroll
        for (int h = 0; h < 2; h++) {
            int row = r0 + wm * 32 + mt * 16 + h * 8 + g4;
            zzr[mt][h] = g_zz[row];
            lb[mt][h] = __uint_as_float(g_bestu[row]);
        }

    const int lrow = ((lane >> 3) & 1) * 8 + (lane & 7);
    const int lcol = (lane >> 4) * 8;
    const float* ees = (const float*)(smem + EE_OFF);

    mbar_wait(sb + MB_A, 0);
    int ph[2] = {0, 0};

    for (int cc = 0; cc < CHUNKS_PER_LAUNCH; cc++) {
        int c = c0 + cc;
        int buf = cc & 1;
        mbar_wait(sb + MB_B + buf * 8, ph[buf]);
        ph[buf] ^= 1;
        // safe to refill buf^1: all warps passed end-of-previous-iteration barrier
        if (tid == 0 && cc + 1 < CHUNKS_PER_LAUNCH) {
            mbar_expect_tx(sb + MB_B + (buf ^ 1) * 8, 65536);
            bulk_cp(sb + B_OFF + (buf ^ 1) * 65536,
                    g_cbb_sw + (size_t)(c + 1) * 65536, 65536, sb + MB_B + (buf ^ 1) * 8);
        }

        const uint32_t bbase = sb + B_OFF + buf * 65536;
        const uint32_t abase = sb + A_OFF;
        float acc[2][4][4];
#pragma unroll
        for (int mt = 0; mt < 2; mt++)
#pragma unroll
            for (int nt = 0; nt < 4; nt++)
#pragma unroll
                for (int e = 0; e < 4; e++) acc[mt][nt][e] = 0.f;

#pragma unroll
        for (int kk = 0; kk < 16; kk++) {
            int k0 = kk * 16 + lcol;
            uint32_t a[2][4], b[2][4];
#pragma unroll
            for (int mt = 0; mt < 2; mt++)
                ldsm_x4(a[mt], tile_addr(abase, wm * 32 + mt * 16 + lrow, k0));
#pragma unroll
            for (int p = 0; p < 2; p++)
                ldsm_x4(b[p], tile_addr(bbase, wn * 32 + p * 16 + lrow, k0));
#pragma unroll
            for (int mt = 0; mt < 2; mt++)
#pragma unroll
                for (int nt = 0; nt < 4; nt++) {
                    int p = nt >> 1, o = nt & 1;
                    mma16816(acc[mt][nt], a[mt], b[p][o], b[p][o + 2]);
                }
        }

        // epilogue: scores, per-row running min, candidate append
        float nb[2][2];
#pragma unroll
        for (int mt = 0; mt < 2; mt++)
#pragma unroll
            for (int h = 0; h < 2; h++) {
                float zze = zzr[mt][h];
                float m = 3.0e38f;
#pragma unroll
                for (int nt = 0; nt < 4; nt++)
#pragma unroll
                    for (int e = 0; e < 2; e++) {
                        int code = c * 128 + wn * 32 + nt * 8 + q4 * 2 + e;
                        float s = fmaf(-2.0f, acc[mt][nt][h * 2 + e], zze + ees[code]);
                        acc[mt][nt][h * 2 + e] = s;
                        m = fminf(m, s);
                    }
                m = fminf(m, __shfl_xor_sync(0xffffffffu, m, 1));
                m = fminf(m, __shfl_xor_sync(0xffffffffu, m, 2));
                nb[mt][h] = fminf(lb[mt][h], m);
            }
#pragma unroll
        for (int mt = 0; mt < 2; mt++)
#pragma unroll
            for (int h = 0; h < 2; h++) {
                float thr = nb[mt][h] + MARGIN;
                int row = r0 + wm * 32 + mt * 16 + h * 8 + g4;
#pragma unroll
                for (int nt = 0; nt < 4; nt++)
#pragma unroll
                    for (int e = 0; e < 2; e++) {
                        float s = acc[mt][nt][h * 2 + e];
                        if (s < thr) {
                            int code = c * 128 + wn * 32 + nt * 8 + q4 * 2 + e;
                            int slot = atomicAdd(&g_cnt[row], 1);
                            if (slot < CANDMAX) {
                                g_cand_s[(size_t)row * CANDMAX + slot] = s;
                                g_cand_c[(size_t)row * CANDMAX + slot] = code;
                            }
                            atomicMin(&g_bestu[row], __float_as_uint(s));
                        }
                    }
                lb[mt][h] = nb[mt][h];
            }
        __syncthreads();   // all warps done reading buf before it is refilled next iter
    }
}

// ---------------- exact fp32 rescore ----------------
__global__ void k_rescore(const float* __restrict__ cb) {
    int row = blockIdx.x * 8 + (threadIdx.x >> 5);
    int lane = threadIdx.x & 31;
    const float4* zr = reinterpret_cast<const float4*>(g_zt + (size_t)row * NC);
    float4 z0 = zr[lane * 2], z1 = zr[lane * 2 + 1];
    float zzr = g_zz[row];
    int cnt = g_cnt[row];
    float bs = __uint_as_float(g_bestu[row]);
    unsigned long long bkey = ~0ull;

    auto eval = [&](int code) {
        const float4* er = reinterpret_cast<const float4*>(cb + (size_t)code * NC);
        float4 e0 = er[lane * 2], e1 = er[lane * 2 + 1];
        float p = z0.x * e0.x + z0.y * e0.y + z0.z * e0.z + z0.w * e0.w
                + z1.x * e1.x + z1.y * e1.y + z1.z * e1.z + z1.w * e1.w;
#pragma unroll
        for (int o = 16; o > 0; o >>= 1) p += __shfl_xor_sync(0xffffffffu, p, o);
        float d = __fadd_rn(__fadd_rn(zzr, g_ee[code]), -2.0f * p);
        unsigned long long key =
            ((unsigned long long)__float_as_uint(d) << 13) | (unsigned long long)code;
        if (key < bkey) bkey = key;
    };

    if (cnt > CANDMAX) {
        for (int code = 0; code < NCODES; code++) eval(code);
    } else {
        size_t crow = (size_t)row * CANDMAX;
        for (int i = 0; i < cnt; i++) {
            float si = g_cand_s[crow + i];
            if (si > bs + MARGIN) continue;
            eval(g_cand_c[crow + i]);
        }
    }
    if (lane == 0) g_idx[row] = (int)(bkey & 8191u);
}

__global__ void k_output(const float* __restrict__ z, const float* __restrict__ cb,
                         float* __restrict__ out) {
    __shared__ float warp_s[8];
    int e = blockIdx.x * 256 + threadIdx.x;
    int t = e & 2047, bc = e >> 11, c = bc & 255, b = bc >> 8;
    int code = g_idx[b * 2048 + t];
    float v = z[e];
    float zq = cb[(size_t)code * NC + c];
    float d = zq - v;
    out[e] = v + d;
    float s = d * d;
#pragma unroll
    for (int o = 16; o > 0; o >>= 1) s += __shfl_xor_sync(0xffffffffu, s, o);
    if ((threadIdx.x & 31) == 0) warp_s[threadIdx.x >> 5] = s;
    __syncthreads();
    if (threadIdx.x == 0) {
        float acc = 0.f;
#pragma unroll
        for (int w = 0; w < 8; w++) acc += warp_s[w];
        g_losspart[blockIdx.x] = acc;
    }
}

__global__ void k_final(float* __restrict__ out) {
    if (blockIdx.x < 128) {
        int i = blockIdx.x * 256 + threadIdx.x;
        out[NQ + i] = (float)g_idx[i];
    } else {
        __shared__ double ds[256];
        double a = 0.0;
        for (int i = threadIdx.x; i < NQ / 256; i += 256) a += (double)g_losspart[i];
        ds[threadIdx.x] = a;
        __syncthreads();
        for (int o = 128; o > 0; o >>= 1) {
            if (threadIdx.x < o) ds[threadIdx.x] += ds[threadIdx.x + o];
            __syncthreads();
        }
        if (threadIdx.x == 0) out[NQ + NROWS] = (float)(ds[0] / (double)NQ);
    }
}

extern "C" void kernel_launch(void* const* d_in, const int* in_sizes, int n_in,
                              void* d_out, int out_size) {
    const float* z  = (const float*)d_in[0];
    const float* cb = (const float*)d_in[1];
    float* out = (float*)d_out;
    cudaFuncSetAttribute(k_screen, cudaFuncAttributeMaxDynamicSharedMemorySize, SMEMT);
    k_transpose<<<NROWS / 64, 256>>>(z);
    k_prep<<<(NCODES * NC) / 256, 256>>>(cb);
    k_norms<<<(NROWS + NCODES) / 8, 256>>>(cb);
    k_screen<<<NROWS / 128, NTHREADS, SMEMT>>>(0);
    k_screen<<<NROWS / 128, NTHREADS, SMEMT>>>(16);
    k_screen<<<NROWS / 128, NTHREADS, SMEMT>>>(32);
    k_screen<<<NROWS / 128, NTHREADS, SMEMT>>>(48);
    k_rescore<<<NROWS / 8, 256>>>(cb);
    k_output<<<NQ / 256, 256>>>(z, cb, out);
    k_final<<<129, 256>>>(out);
}